// round 2
// baseline (speedup 1.0000x reference)
#include <cuda_runtime.h>
#include <cuda_bf16.h>

// Problem constants (from reference): x,y [4096, 16, 128] f32, out [4096, 99, 128] f32.
#define N_EDGES   4096
#define DIM_IN    16
#define DIM_OUT   99
#define CHANNELS  128
#define VGROUPS   (CHANNELS / 4)   // 32 float4 groups per channel dim

#define MAX_ROW   64               // max CG entries contributing to one output index
#define NNZ_MAX   8192

// Scratch for the CSR (per-output-row) representation of the COO CG metadata.
__device__ int   g_row_cnt[DIM_OUT];
__device__ int   g_row_idx[DIM_OUT * MAX_ROW];   // mu1 | (mu2 << 8)
__device__ float g_row_cg [DIM_OUT * MAX_ROW];

// Deterministic CSR build: thread k scans the COO in j-order and collects its
// row. Order within each row is fixed (ascending j), so the later floating
// summation order is identical on every call — no atomics anywhere.
__global__ void build_csr_kernel(const int* __restrict__ mu1,
                                 const int* __restrict__ mu2,
                                 const int* __restrict__ mu3,
                                 const float* __restrict__ cg,
                                 int nnz)
{
    int k = threadIdx.x;
    if (k >= DIM_OUT) return;
    int cnt = 0;
    for (int j = 0; j < nnz; ++j) {
        if (mu3[j] == k) {
            if (cnt < MAX_ROW) {
                g_row_idx[k * MAX_ROW + cnt] = (mu1[j] & 0xff) | ((mu2[j] & 0xff) << 8);
                g_row_cg [k * MAX_ROW + cnt] = cg[j];
            }
            ++cnt;
        }
    }
    g_row_cnt[k] = (cnt > MAX_ROW) ? MAX_ROW : cnt;
}

// Main kernel: one block per edge.
//  - stage x[n] and y[n] tiles (16 x 32 float4 each) into shared memory
//  - work item = (k, g): output row k (0..98), float4 channel group g (0..31)
//  - item = k*32 + g  =>  each warp has uniform k, lanes span g  =>  coalesced
//    512B stores per row, broadcast CSR reads, conflict-free smem reads.
// Every one of the 99*32 output vectors is written exactly once (rows with no
// CG entries write zeros), so no output pre-zeroing is needed.
__global__ __launch_bounds__(256)
void tp_main_kernel(const float4* __restrict__ x,
                    const float4* __restrict__ y,
                    float4* __restrict__ out)
{
    __shared__ float4 xs[DIM_IN * VGROUPS];   // 16*32 float4 = 8 KB
    __shared__ float4 ys[DIM_IN * VGROUPS];   // 8 KB

    const int n   = blockIdx.x;
    const int tid = threadIdx.x;

    // Cooperative tile load: 512 float4 per tensor, 256 threads -> 2 each.
    const float4* xb = x + (size_t)n * (DIM_IN * VGROUPS);
    const float4* yb = y + (size_t)n * (DIM_IN * VGROUPS);
#pragma unroll
    for (int i = tid; i < DIM_IN * VGROUPS; i += 256) {
        xs[i] = xb[i];
        ys[i] = yb[i];
    }
    __syncthreads();

    float4* ob = out + (size_t)n * (DIM_OUT * VGROUPS);

    for (int item = tid; item < DIM_OUT * VGROUPS; item += 256) {
        const int k = item >> 5;        // output index 0..98 (uniform per warp)
        const int g = item & 31;        // float4 channel group (lane id)

        const int cnt = g_row_cnt[k];
        float4 acc = make_float4(0.f, 0.f, 0.f, 0.f);

#pragma unroll 4
        for (int j = 0; j < cnt; ++j) {
            const int   p = g_row_idx[k * MAX_ROW + j];
            const float c = g_row_cg [k * MAX_ROW + j];
            const float4 a = xs[(p & 0xff) * VGROUPS + g];
            const float4 b = ys[((p >> 8) & 0xff) * VGROUPS + g];
            acc.x = fmaf(c * a.x, b.x, acc.x);
            acc.y = fmaf(c * a.y, b.y, acc.y);
            acc.z = fmaf(c * a.z, b.z, acc.z);
            acc.w = fmaf(c * a.w, b.w, acc.w);
        }
        ob[item] = acc;
    }
}

extern "C" void kernel_launch(void* const* d_in, const int* in_sizes, int n_in,
                              void* d_out, int out_size)
{
    const float* x   = (const float*)d_in[0];
    const float* y   = (const float*)d_in[1];
    const int*   mu1 = (const int*)  d_in[2];
    const int*   mu2 = (const int*)  d_in[3];
    const int*   mu3 = (const int*)  d_in[4];
    const float* cg  = (const float*)d_in[5];

    int nnz = in_sizes[5];
    if (nnz > NNZ_MAX) nnz = NNZ_MAX;

    build_csr_kernel<<<1, 128>>>(mu1, mu2, mu3, cg, nnz);

    tp_main_kernel<<<N_EDGES, 256>>>((const float4*)x,
                                     (const float4*)y,
                                     (float4*)d_out);
}

// round 3
// speedup vs baseline: 1.0421x; 1.0421x over previous
#include <cuda_runtime.h>
#include <cuda_bf16.h>

// Problem constants: x,y [4096, 16, 128] f32, out [4096, 99, 128] f32.
#define N_EDGES   4096
#define DIM_IN    16
#define DIM_OUT   99
#define CHANNELS  128
#define VGROUPS   (CHANNELS / 4)   // 32 float4 groups

#define MAX_ROW   32               // max CG entries contributing to one output index
#define NNZ_CAP   2048

// CSR (per-output-row) representation of the COO CG metadata.
__device__ int   g_row_cnt[DIM_OUT];
__device__ int   g_row_idx[DIM_OUT * MAX_ROW];   // (mu1*32) | ((mu2*32) << 16)  (float4 indices)
__device__ float g_row_cg [DIM_OUT * MAX_ROW];

// Parallel deterministic CSR build.
// Stage the COO in shared (coalesced), then thread j finds its within-row
// position by counting earlier entries with the same mu3 (preserves j-order,
// so the main kernel's summation order is identical every call; no atomics).
__global__ void build_csr_kernel(const int* __restrict__ mu1,
                                 const int* __restrict__ mu2,
                                 const int* __restrict__ mu3,
                                 const float* __restrict__ cg,
                                 int nnz)
{
    __shared__ int   s1[NNZ_CAP];
    __shared__ int   s2[NNZ_CAP];
    __shared__ int   s3[NNZ_CAP];
    __shared__ float sc[NNZ_CAP];

    const int tid = threadIdx.x;
    const int nt  = blockDim.x;

    // zero row counts (rows with no entries must read cnt=0)
    if (tid < DIM_OUT) g_row_cnt[tid] = 0;

    for (int j = tid; j < nnz; j += nt) {
        s1[j] = mu1[j];
        s2[j] = mu2[j];
        s3[j] = mu3[j];
        sc[j] = cg[j];
    }
    __syncthreads();

    for (int j = tid; j < nnz; j += nt) {
        const int k = s3[j];
        int pos = 0;
        for (int i = 0; i < j; ++i) pos += (s3[i] == k);
        if (pos < MAX_ROW) {
            g_row_idx[k * MAX_ROW + pos] = (s1[j] * VGROUPS) | ((s2[j] * VGROUPS) << 16);
            g_row_cg [k * MAX_ROW + pos] = sc[j];
        }
        // last entry of this row writes the count
        bool last = true;
        for (int i = j + 1; i < nnz; ++i)
            if (s3[i] == k) { last = false; break; }
        if (last) g_row_cnt[k] = (pos + 1 > MAX_ROW) ? MAX_ROW : (pos + 1);
    }
}

// Main kernel: one block per edge, 352 threads = 11 warps.
// Warp w owns output rows [9w, 9w+9); lanes span the 32 float4 channel groups.
// 11*9 = 99 rows, every thread does exactly 9 items -> no ragged remainder.
// Each output vector is written exactly once (empty rows write zeros), so no
// output pre-zeroing is needed.
__global__ __launch_bounds__(352)
void tp_main_kernel(const float4* __restrict__ x,
                    const float4* __restrict__ y,
                    float4* __restrict__ out)
{
    __shared__ float4 xs[DIM_IN * VGROUPS];   // 8 KB
    __shared__ float4 ys[DIM_IN * VGROUPS];   // 8 KB

    const int n    = blockIdx.x;
    const int tid  = threadIdx.x;
    const int w    = tid >> 5;      // warp 0..10
    const int lane = tid & 31;      // channel group g

    const float4* xb = x + (size_t)n * (DIM_IN * VGROUPS);
    const float4* yb = y + (size_t)n * (DIM_IN * VGROUPS);
    for (int i = tid; i < DIM_IN * VGROUPS; i += 352) {
        xs[i] = xb[i];
        ys[i] = yb[i];
    }
    __syncthreads();

    const float4* xg = xs + lane;   // xg[off] with off = mu1*32
    const float4* yg = ys + lane;

    float4* ob = out + (size_t)n * (DIM_OUT * VGROUPS) + lane;

    const int k0 = w * 9;
#pragma unroll
    for (int r = 0; r < 9; ++r) {
        const int k   = k0 + r;                 // uniform per warp
        const int cnt = g_row_cnt[k];

        float4 acc = make_float4(0.f, 0.f, 0.f, 0.f);
        const int* rowi = g_row_idx + k * MAX_ROW;
        const float* rowc = g_row_cg + k * MAX_ROW;

#pragma unroll 2
        for (int j = 0; j < cnt; ++j) {
            const int   p = rowi[j];            // uniform (L1 broadcast)
            const float c = rowc[j];
            const float4 a = xg[p & 0xffff];
            const float4 b = yg[p >> 16];
            acc.x = fmaf(c * a.x, b.x, acc.x);
            acc.y = fmaf(c * a.y, b.y, acc.y);
            acc.z = fmaf(c * a.z, b.z, acc.z);
            acc.w = fmaf(c * a.w, b.w, acc.w);
        }
        ob[(size_t)k * VGROUPS] = acc;
    }
}

extern "C" void kernel_launch(void* const* d_in, const int* in_sizes, int n_in,
                              void* d_out, int out_size)
{
    const float* x   = (const float*)d_in[0];
    const float* y   = (const float*)d_in[1];
    const int*   mu1 = (const int*)  d_in[2];
    const int*   mu2 = (const int*)  d_in[3];
    const int*   mu3 = (const int*)  d_in[4];
    const float* cg  = (const float*)d_in[5];

    int nnz = in_sizes[5];
    if (nnz > NNZ_CAP) nnz = NNZ_CAP;

    build_csr_kernel<<<1, 1024>>>(mu1, mu2, mu3, cg, nnz);

    tp_main_kernel<<<N_EDGES, 352>>>((const float4*)x,
                                     (const float4*)y,
                                     (float4*)d_out);
}

// round 4
// speedup vs baseline: 1.3284x; 1.2747x over previous
#include <cuda_runtime.h>
#include <cuda_bf16.h>

// Problem constants: x,y [4096, 16, 128] f32, out [4096, 99, 128] f32.
#define N_EDGES   4096
#define DIM_IN    16
#define DIM_OUT   99
#define CHANNELS  128
#define VGROUPS   (CHANNELS / 4)   // 32 float4 groups (= warp width)
#define NNZ_CAP   2048

#define NWARPS    9
#define NTHREADS  (NWARPS * 32)    // 288
#define ROWS_PER_WARP 11           // 9 * 11 = 99

// Compact CSR of the CG metadata.
//  g_off[k]..g_off[k+1] : entries of output row k
//  entry.x = (mu1*512) | ((mu2*512) << 16)   (byte offsets of float4 rows)
//  entry.y = __float_as_int(cg)
__device__ int  g_off[DIM_OUT + 1];
__device__ int2 g_ent[NNZ_CAP];

// Deterministic, atomic-free compact-CSR build (single block).
__global__ void build_csr_kernel(const int* __restrict__ mu1,
                                 const int* __restrict__ mu2,
                                 const int* __restrict__ mu3,
                                 const float* __restrict__ cg,
                                 int nnz)
{
    __shared__ int   s1[NNZ_CAP];
    __shared__ int   s2[NNZ_CAP];
    __shared__ int   s3[NNZ_CAP];
    __shared__ float sc[NNZ_CAP];
    __shared__ int   s_cnt[DIM_OUT];
    __shared__ int   s_off[DIM_OUT + 1];

    const int tid = threadIdx.x;
    const int nt  = blockDim.x;

    for (int j = tid; j < nnz; j += nt) {
        s1[j] = mu1[j];
        s2[j] = mu2[j];
        s3[j] = mu3[j];
        sc[j] = cg[j];
    }
    __syncthreads();

    // per-row counts
    if (tid < DIM_OUT) {
        int c = 0;
        for (int j = 0; j < nnz; ++j) c += (s3[j] == tid);
        s_cnt[tid] = c;
    }
    __syncthreads();

    // serial exclusive prefix sum (99 adds, trivial)
    if (tid == 0) {
        int acc = 0;
        for (int k = 0; k < DIM_OUT; ++k) { s_off[k] = acc; acc += s_cnt[k]; }
        s_off[DIM_OUT] = acc;
    }
    __syncthreads();

    if (tid <= DIM_OUT) g_off[tid] = s_off[tid];

    // scatter: position of entry j inside its row = #earlier entries with same mu3
    // (preserves original j-order => bit-identical summation order every call)
    for (int j = tid; j < nnz; j += nt) {
        const int k = s3[j];
        int pos = 0;
        for (int i = 0; i < j; ++i) pos += (s3[i] == k);
        g_ent[s_off[k] + pos] = make_int2((s1[j] * (VGROUPS * 16)) |
                                          ((s2[j] * (VGROUPS * 16)) << 16),
                                          __float_as_int(sc[j]));
    }
}

// Main kernel: one block per edge, 288 threads = 9 warps.
// Warp w owns rows k = w + 9r, r=0..10 (interleaved for load balance);
// lanes span the 32 float4 channel groups.
// Every output vector is written exactly once (empty rows write zeros).
__global__ __launch_bounds__(NTHREADS)
void tp_main_kernel(const float4* __restrict__ x,
                    const float4* __restrict__ y,
                    float4* __restrict__ out)
{
    __shared__ float4 xs[DIM_IN * VGROUPS];   // 8 KB
    __shared__ float4 ys[DIM_IN * VGROUPS];   // 8 KB
    __shared__ int2   se[NNZ_CAP];            // 16 KB (only nnz used)
    __shared__ int    so[DIM_OUT + 1];

    const int n    = blockIdx.x;
    const int tid  = threadIdx.x;
    const int w    = tid >> 5;
    const int lane = tid & 31;

    // stage input tiles
    const float4* xb = x + (size_t)n * (DIM_IN * VGROUPS);
    const float4* yb = y + (size_t)n * (DIM_IN * VGROUPS);
    for (int i = tid; i < DIM_IN * VGROUPS; i += NTHREADS) {
        xs[i] = xb[i];
        ys[i] = yb[i];
    }

    // stage CSR
    if (tid <= DIM_OUT) so[tid] = g_off[tid];
    __syncthreads();
    const int total = so[DIM_OUT];
    for (int i = tid; i < total; i += NTHREADS) se[i] = g_ent[i];
    __syncthreads();

    const char* xc = (const char*)xs + lane * 16;
    const char* yc = (const char*)ys + lane * 16;

    float4* ob = out + (size_t)n * (DIM_OUT * VGROUPS) + lane;

#pragma unroll
    for (int r = 0; r < ROWS_PER_WARP; ++r) {
        const int k   = w + NWARPS * r;       // uniform per warp
        const int beg = so[k];
        const int end = so[k + 1];

        float4 acc = make_float4(0.f, 0.f, 0.f, 0.f);

#pragma unroll 4
        for (int j = beg; j < end; ++j) {
            const int2  e = se[j];            // LDS.64 broadcast
            const float c = __int_as_float(e.y);
            const float4 a = *(const float4*)(xc + (e.x & 0xffff));
            const float4 b = *(const float4*)(yc + (e.x >> 16));
            acc.x = fmaf(c * a.x, b.x, acc.x);
            acc.y = fmaf(c * a.y, b.y, acc.y);
            acc.z = fmaf(c * a.z, b.z, acc.z);
            acc.w = fmaf(c * a.w, b.w, acc.w);
        }
        ob[(size_t)k * VGROUPS] = acc;
    }
}

extern "C" void kernel_launch(void* const* d_in, const int* in_sizes, int n_in,
                              void* d_out, int out_size)
{
    const float* x   = (const float*)d_in[0];
    const float* y   = (const float*)d_in[1];
    const int*   mu1 = (const int*)  d_in[2];
    const int*   mu2 = (const int*)  d_in[3];
    const int*   mu3 = (const int*)  d_in[4];
    const float* cg  = (const float*)d_in[5];

    int nnz = in_sizes[5];
    if (nnz > NNZ_CAP) nnz = NNZ_CAP;

    build_csr_kernel<<<1, 1024>>>(mu1, mu2, mu3, cg, nnz);

    tp_main_kernel<<<N_EDGES, NTHREADS>>>((const float4*)x,
                                          (const float4*)y,
                                          (float4*)d_out);
}